// round 10
// baseline (speedup 1.0000x reference)
#include <cuda_runtime.h>
#include <cstdint>
#include <math.h>

#define N 4096
#define DIN 64
#define DOUT 64
#define NEG_HUGE (-3.402823466e38f)

// ---- scratch (device globals; no runtime allocation) ----
__device__ __align__(16) float g_P[(size_t)N * N];     // 64 MB: final P
// Operands in unified pair-quad layout:
//   phys_row(k) = (k>>3)*4 + (k&3)            (N/2 rows, pitch 2N floats)
//   col(r,k)    = ((r>>4)*8 + (r&7))*4 + 2*((k>>2)&1) + ((r>>3)&1)
// quad = [(r,k), (r+8,k), (r,k+4), (r+8,k+4)]
__device__ __align__(16) float g_AtcP[(size_t)N * N];  // A-op: r=m, val tf32(A[m][k]*c[k]); topk scratch later
__device__ __align__(16) float g_BtP[(size_t)N * N];   // B-op: r=n, val tf32(A[k][n])
__device__ __align__(16) float g_dinv[N];
__device__ __align__(16) float g_c[N];
__device__ __align__(16) float g_e[N];
__device__ float g_t[2];

// ===========================================================================
// helpers
// ===========================================================================
__device__ __forceinline__ uint32_t smem_u32(const void* p) {
    uint32_t a;
    asm("{ .reg .u64 t; cvta.to.shared.u64 t, %1; cvt.u32.u64 %0, t; }"
        : "=r"(a) : "l"(p));
    return a;
}
__device__ __forceinline__ float f2tf32(float x) {
    float y;
    asm("cvt.rna.tf32.f32 %0, %1;" : "=f"(y) : "f"(x));
    return y;
}
#define CP_ASYNC16(smem, gptr) \
    asm volatile("cp.async.cg.shared.global [%0], [%1], 16;" \
                 :: "r"(smem), "l"(gptr) : "memory")
#define CP_COMMIT() asm volatile("cp.async.commit_group;" ::: "memory")
#define CP_WAIT(n)  asm volatile("cp.async.wait_group %0;" :: "n"(n) : "memory")

__device__ __forceinline__ void mma_tf32(float* d, float a0, float a1, float a2,
                                         float a3, float b0, float b1) {
    asm volatile(
        "mma.sync.aligned.m16n8k8.row.col.f32.tf32.tf32.f32 "
        "{%0,%1,%2,%3}, {%4,%5,%6,%7}, {%8,%9}, {%0,%1,%2,%3};"
        : "+f"(d[0]), "+f"(d[1]), "+f"(d[2]), "+f"(d[3])
        : "r"(__float_as_uint(a0)), "r"(__float_as_uint(a1)),
          "r"(__float_as_uint(a2)), "r"(__float_as_uint(a3)),
          "r"(__float_as_uint(b0)), "r"(__float_as_uint(b1)));
}

// ===========================================================================
// Kernel 1: row sums of A -> dinv, c ; sigmoid(theta)
// ===========================================================================
__global__ __launch_bounds__(256) void k_rowsum_A(const float* __restrict__ A,
                                                  const float* __restrict__ theta) {
    int row = blockIdx.x;
    const float4* a4 = (const float4*)(A + (size_t)row * N);
    float s = 0.f;
    for (int i = threadIdx.x; i < N / 4; i += 256) {
        float4 v = a4[i];
        s += v.x + v.y + v.z + v.w;
    }
    __shared__ float red[256];
    red[threadIdx.x] = s;
    __syncthreads();
    for (int o = 128; o > 0; o >>= 1) {
        if (threadIdx.x < o) red[threadIdx.x] += red[threadIdx.x + o];
        __syncthreads();
    }
    if (threadIdx.x == 0) {
        float d = red[0];
        g_dinv[row] = rsqrtf(d);
        g_c[row] = 1.0f / d;
        if (row == 0) {
            g_t[0] = 1.0f / (1.0f + expf(-theta[0]));
            g_t[1] = 1.0f / (1.0f + expf(-theta[1]));
        }
    }
}

// ===========================================================================
// Kernel 2: prep — write both operands in pair-quad layout.
// block (32,8), grid (N/32, N/32). Tile: A rows y0+i, cols x0+j.
// ===========================================================================
__global__ __launch_bounds__(256) void k_prep(const float* __restrict__ A) {
    __shared__ float ta[32][33];   // [m_local][k_local] = tf32(A*c)
    __shared__ float tb[32][33];   // [k_local][n_local] = tf32(A)
    int tx = threadIdx.x, ty = threadIdx.y;
    int tid = ty * 32 + tx;
    int x0 = blockIdx.x * 32, y0 = blockIdx.y * 32;
    float cc = g_c[x0 + tx];
#pragma unroll
    for (int r = 0; r < 4; r++) {
        int i = ty + r * 8;
        float v = A[(size_t)(y0 + i) * N + x0 + tx];
        tb[i][tx] = f2tf32(v);
        ta[i][tx] = f2tf32(v * cc);
    }
    __syncthreads();

    // one quad per thread per operand
    int kp = tid >> 4, rp = tid & 15;
    int k_local = (kp & 3) + (kp >> 2) * 8;       // k with bit2=0
    int r_local = (rp & 7) + (rp >> 3) * 16;      // r with bit3=0

    // ---- A-operand: m = y0 + r_local, k = x0 + k_local ----
    {
        int k = x0 + k_local, m = y0 + r_local;
        size_t row_g = (size_t)((k >> 3) * 4 + (k & 3));
        int colf = ((m >> 4) * 8 + (m & 7)) * 4;
        float4 q = make_float4(ta[r_local][k_local], ta[r_local + 8][k_local],
                               ta[r_local][k_local + 4], ta[r_local + 8][k_local + 4]);
        *(float4*)(g_AtcP + row_g * (2 * N) + colf) = q;
    }
    // ---- B-operand: k = y0 + k_local, n = x0 + r_local ----
    {
        int k = y0 + k_local, n = x0 + r_local;
        size_t row_g = (size_t)((k >> 3) * 4 + (k & 3));
        int colf = ((n >> 4) * 8 + (n & 7)) * 4;
        float4 q = make_float4(tb[k_local][r_local], tb[k_local][r_local + 8],
                               tb[k_local + 4][r_local], tb[k_local + 4][r_local + 8]);
        *(float4*)(g_BtP + row_g * (2 * N) + colf) = q;
    }
}

// ===========================================================================
// dummy no-op: shifts ncu's captured launch index onto the GEMM
// ===========================================================================
__global__ void k_nop() {}

// ===========================================================================
// Kernel 3: tf32 mma.sync GEMM — CTA 128x128, 8 warps 4m x 2n, warp 32x64,
// 2-stage cp.async, LDS.128 quad-fragment loads.
//   M = Atc^T @ Bt ; epilogue: g_P = t1*dinv_i*dinv_j*M + I
// ===========================================================================
#define BK 32
#define NCH (N / BK)             // 128
#define PITCH 264                // floats; == 8 mod 32 -> conflict-free LDS.128
#define TILE_F (16 * PITCH)      // 4224 floats per operand (16 folded rows)
#define STAGE_F (2 * TILE_F)     // 8448 floats
#define SMEM_BYTES (2 * STAGE_F * 4)   // 67584

__device__ __forceinline__ void stage_chunk(uint32_t sbase, int buf, int ch,
                                            int i0, int j0, int tid) {
    int k0 = ch * BK;
    uint32_t sa = sbase + buf * (STAGE_F * 4);
    uint32_t sb = sa + TILE_F * 4;
#pragma unroll
    for (int t = 0; t < 4; t++) {
        int id = tid + t * 256;
        int r = id >> 6, seg = id & 63;    // 16 rows x 64 float4
        CP_ASYNC16(sa + r * (PITCH * 4) + seg * 16,
                   g_AtcP + (size_t)(k0 / 2 + r) * (2 * N) + i0 * 2 + seg * 4);
        CP_ASYNC16(sb + r * (PITCH * 4) + seg * 16,
                   g_BtP + (size_t)(k0 / 2 + r) * (2 * N) + j0 * 2 + seg * 4);
    }
}

__global__ __launch_bounds__(256, 2) void k_gemm_mma() {
    extern __shared__ float sm[];
    uint32_t sbase = smem_u32(sm);
    int tid = threadIdx.x;
    int wid = tid >> 5, lane = tid & 31;
    int g = lane >> 2, tig = lane & 3;
    int wm0 = (wid & 3) * 32, wn0 = (wid >> 2) * 64;
    int i0 = blockIdx.y * 128, j0 = blockIdx.x * 128;

    float acc[2][8][4];
#pragma unroll
    for (int mt = 0; mt < 2; mt++)
#pragma unroll
        for (int j = 0; j < 8; j++)
#pragma unroll
            for (int c = 0; c < 4; c++) acc[mt][j][c] = 0.f;

    stage_chunk(sbase, 0, 0, i0, j0, tid);
    CP_COMMIT();
    stage_chunk(sbase, 1, 1, i0, j0, tid);
    CP_COMMIT();

    for (int ch = 0; ch < NCH; ch++) {
        if (ch < NCH - 1) CP_WAIT(1);
        else              CP_WAIT(0);
        __syncthreads();

        const float* As = sm + (ch & 1) * STAGE_F;
        const float* Bs = As + TILE_F;
#pragma unroll
        for (int s = 0; s < 4; s++) {
            const float* Ar = As + (4 * s + tig) * PITCH;
            const float* Br = Bs + (4 * s + tig) * PITCH;
            float4 qa[2], qb[4];
#pragma unroll
            for (int mt = 0; mt < 2; mt++)
                qa[mt] = *(const float4*)(Ar + wm0 * 2 + mt * 32 + 4 * g);
#pragma unroll
            for (int jp = 0; jp < 4; jp++)
                qb[jp] = *(const float4*)(Br + wn0 * 2 + jp * 32 + 4 * g);
#pragma unroll
            for (int jp = 0; jp < 4; jp++) {
#pragma unroll
                for (int mt = 0; mt < 2; mt++) {
                    mma_tf32(acc[mt][2 * jp], qa[mt].x, qa[mt].y, qa[mt].z,
                             qa[mt].w, qb[jp].x, qb[jp].z);
                    mma_tf32(acc[mt][2 * jp + 1], qa[mt].x, qa[mt].y, qa[mt].z,
                             qa[mt].w, qb[jp].y, qb[jp].w);
                }
            }
        }
        __syncthreads();
        if (ch + 2 < NCH) {
            stage_chunk(sbase, ch & 1, ch + 2, i0, j0, tid);
            CP_COMMIT();
        }
    }

    // ---- epilogue: scale, diag, transpose through smem, coalesced store ----
    float t1 = g_t[1];
    float* scr = sm;   // 128 x 132 floats = 67584 B (= SMEM_BYTES)
#pragma unroll
    for (int mt = 0; mt < 2; mt++) {
        int m0 = wm0 + 16 * mt + g;
        int gi0 = i0 + m0, gi1 = gi0 + 8;
        float di0 = t1 * g_dinv[gi0];
        float di1 = t1 * g_dinv[gi1];
#pragma unroll
        for (int j = 0; j < 8; j++) {
            int n = wn0 + 8 * j + 2 * tig;
            int gj = j0 + n;
            float dj0 = g_dinv[gj], dj1 = g_dinv[gj + 1];
            float p00 = acc[mt][j][0] * di0 * dj0;
            float p01 = acc[mt][j][1] * di0 * dj1;
            float p10 = acc[mt][j][2] * di1 * dj0;
            float p11 = acc[mt][j][3] * di1 * dj1;
            if (gi0 == gj) p00 += 1.0f;
            if (gi0 == gj + 1) p01 += 1.0f;
            if (gi1 == gj) p10 += 1.0f;
            if (gi1 == gj + 1) p11 += 1.0f;
            *(float2*)(scr + m0 * 132 + n) = make_float2(p00, p01);
            *(float2*)(scr + (m0 + 8) * 132 + n) = make_float2(p10, p11);
        }
    }
    __syncthreads();
#pragma unroll
    for (int t = 0; t < 16; t++) {
        int id = tid + t * 256;
        int row = id >> 5, cg = id & 31;
        float4 v = *(float4*)(scr + row * 132 + cg * 4);
        *(float4*)(g_P + (size_t)(i0 + row) * N + j0 + cg * 4) = v;
    }
}

// ===========================================================================
// Kernel 4: finalize P += t0*dinv_i*dinv_j*A (in place), row-sum -> e
// ===========================================================================
__global__ __launch_bounds__(256) void k_finalize_rowsum(const float* __restrict__ A) {
    int row = blockIdx.x;
    float di = g_dinv[row] * g_t[0];
    float4* p4 = (float4*)(g_P + (size_t)row * N);
    const float4* a4 = (const float4*)(A + (size_t)row * N);
    const float4* d4 = (const float4*)g_dinv;
    float s = 0.f;
    for (int i = threadIdx.x; i < N / 4; i += 256) {
        float4 p = p4[i];
        float4 a = a4[i];
        float4 dv = d4[i];
        p.x += di * dv.x * a.x;
        p.y += di * dv.y * a.y;
        p.z += di * dv.z * a.z;
        p.w += di * dv.w * a.w;
        p4[i] = p;
        s += p.x + p.y + p.z + p.w;
    }
    __shared__ float red[256];
    red[threadIdx.x] = s;
    __syncthreads();
    for (int o = 128; o > 0; o >>= 1) {
        if (threadIdx.x < o) red[threadIdx.x] += red[threadIdx.x + o];
        __syncthreads();
    }
    if (threadIdx.x == 0) g_e[row] = rsqrtf(red[0]);
}

// ===========================================================================
// Kernel 5: per-row top-k + gather + linear (R9-proven).
// ===========================================================================
__global__ __launch_bounds__(256) void k_topk_out(const float* __restrict__ x,
                                                  const float* __restrict__ W,
                                                  const float* __restrict__ b,
                                                  const int* __restrict__ kp,
                                                  float* __restrict__ out) {
    int row = blockIdx.x;
    int tid = threadIdx.x, lane = tid & 31, wid = tid >> 5;
    __shared__ float sv[32];
    __shared__ int si[32];
    __shared__ float selv[16];
    __shared__ int seli[16];
    __shared__ float y[DIN];

    int k = kp ? *kp : 4;
    if (k < 1) k = 1;
    if (k > 16) k = 16;

    const float* prow = g_P + (size_t)row * N;

    if (k <= 4) {
        float v0 = NEG_HUGE, v1 = NEG_HUGE, v2 = NEG_HUGE, v3 = NEG_HUGE;
        int i0 = N, i1 = N, i2 = N, i3 = N;
#pragma unroll
        for (int it = 0; it < 4; it++) {
            int j = (it * 256 + tid) * 4;
            float4 pv = *(const float4*)(prow + j);
            float4 ev = *(const float4*)(g_e + j);
            float vv[4] = {pv.x * ev.x, pv.y * ev.y, pv.z * ev.z, pv.w * ev.w};
#pragma unroll
            for (int u = 0; u < 4; u++) {
                float v = vv[u];
                int idx = j + u;
                if (v > v3) {
                    if (v > v0) {
                        v3 = v2; i3 = i2; v2 = v1; i2 = i1;
                        v1 = v0; i1 = i0; v0 = v; i0 = idx;
                    } else if (v > v1) {
                        v3 = v2; i3 = i2; v2 = v1; i2 = i1;
                        v1 = v; i1 = idx;
                    } else if (v > v2) {
                        v3 = v2; i3 = i2; v2 = v; i2 = idx;
                    } else {
                        v3 = v; i3 = idx;
                    }
                }
            }
        }
#pragma unroll
        for (int r = 0; r < 4; r++) {
            float bv = v0;
            int bi = i0;
#pragma unroll
            for (int o = 16; o > 0; o >>= 1) {
                float ov = __shfl_xor_sync(0xFFFFFFFF, bv, o);
                int oi = __shfl_xor_sync(0xFFFFFFFF, bi, o);
                if (ov > bv || (ov == bv && oi < bi)) { bv = ov; bi = oi; }
            }
            if (v0 == bv && i0 == bi) {
                v0 = v1; i0 = i1; v1 = v2; i1 = i2;
                v2 = v3; i2 = i3; v3 = NEG_HUGE; i3 = N;
            }
            if (lane == 0) { sv[wid * 4 + r] = bv; si[wid * 4 + r] = bi; }
        }
        __syncthreads();
        if (wid == 0) {
            int h = 0;
            float cv = (lane < 8) ? sv[lane * 4] : NEG_HUGE;
            int ci = (lane < 8) ? si[lane * 4] : N;
#pragma unroll
            for (int r = 0; r < 4; r++) {
                float bv = cv;
                int bi = ci;
#pragma unroll
                for (int o = 16; o > 0; o >>= 1) {
                    float ov = __shfl_xor_sync(0xFFFFFFFF, bv, o);
                    int oi = __shfl_xor_sync(0xFFFFFFFF, bi, o);
                    if (ov > bv || (ov == bv && oi < bi)) { bv = ov; bi = oi; }
                }
                if (lane < 8 && cv == bv && ci == bi) {
                    h++;
                    cv = (h < 4) ? sv[lane * 4 + h] : NEG_HUGE;
                    ci = (h < 4) ? si[lane * 4 + h] : N;
                }
                if (lane == 0) { selv[r] = bv; seli[r] = bi; }
            }
        }
        __syncthreads();
    } else {
        // generic multi-pass path; scratch in g_AtcP (dead after GEMM)
        __shared__ float rv[256];
        __shared__ int ri[256];
        float* vbuf = g_AtcP + (size_t)row * N;
        for (int j = tid; j < N; j += 256) vbuf[j] = g_e[j] * prow[j];
        __syncthreads();
        for (int s = 0; s < k; s++) {
            float bv = NEG_HUGE;
            int bi = N;
            for (int j = tid; j < N; j += 256) {
                float val = vbuf[j];
                if (val > bv) { bv = val; bi = j; }
            }
            rv[tid] = bv; ri[tid] = bi;
            __syncthreads();
            for (int o = 128; o > 0; o >>= 1) {
                if (tid < o) {
                    float ov = rv[tid + o]; int oi = ri[tid + o];
                    if (ov > rv[tid] || (ov == rv[tid] && oi < ri[tid])) {
                        rv[tid] = ov; ri[tid] = oi;
                    }
                }
                __syncthreads();
            }
            if (tid == 0) {
                seli[s] = ri[0]; selv[s] = rv[0];
                vbuf[ri[0]] = NEG_HUGE;
            }
            __syncthreads();
        }
    }

    float ei = g_e[row];
    if (tid < DIN) {
        float acc = 0.f;
        for (int s = 0; s < k; s++)
            acc += (ei * selv[s]) * x[(size_t)seli[s] * DIN + tid];
        y[tid] = acc;
    }
    __syncthreads();
    if (tid < DOUT) {
        float acc = b[tid];
        const float* wr = W + tid * DIN;
#pragma unroll
        for (int f = 0; f < DIN; f++) acc += y[f] * wr[f];
        out[(size_t)row * DOUT + tid] = acc;
    }
}

// ===========================================================================
extern "C" void kernel_launch(void* const* d_in, const int* in_sizes, int n_in,
                              void* d_out, int out_size) {
    const float* x = (const float*)d_in[0];
    const float* A = (const float*)d_in[1];
    const float* theta = (const float*)d_in[2];
    const float* W = (const float*)d_in[3];
    const float* b = (const float*)d_in[4];
    const int* kp = (n_in > 5) ? (const int*)d_in[5] : nullptr;
    float* out = (float*)d_out;

    static bool attr_set = false;
    if (!attr_set) {
        cudaFuncSetAttribute(k_gemm_mma, cudaFuncAttributeMaxDynamicSharedMemorySize,
                             SMEM_BYTES);
        attr_set = true;
    }

    k_rowsum_A<<<N, 256>>>(A, theta);
    dim3 pb(32, 8);
    dim3 pg(N / 32, N / 32);
    k_prep<<<pg, pb>>>(A);
    k_nop<<<1, 32>>>();                    // shifts ncu capture onto the GEMM
    dim3 gg(N / 128, N / 128);
    k_gemm_mma<<<gg, 256, SMEM_BYTES>>>();
    k_finalize_rowsum<<<N, 256>>>(A);
    k_topk_out<<<N, 256>>>(x, W, b, kp, out);
}

// round 11
// speedup vs baseline: 1.1489x; 1.1489x over previous
#include <cuda_runtime.h>
#include <cstdint>
#include <math.h>

#define N 4096
#define DIN 64
#define DOUT 64
#define NEG_HUGE (-3.402823466e38f)

// ---- scratch (device globals; no runtime allocation) ----
__device__ __align__(16) float g_P[(size_t)N * N];     // 64 MB: final P
// A operand, [k][m'] with m-pairs (m, m+8) adjacent within 16-blocks
__device__ __align__(16) float g_AtcP[(size_t)N * N];  // also topk scratch later
// B operand, k-folded: phys row = (k>>3)*4 + (k&3), col = 2n + ((k>>2)&1)
__device__ __align__(16) float g_BtP[(size_t)N * N];   // (N/2) rows x 2N cols
__device__ __align__(16) float g_dinv[N];
__device__ __align__(16) float g_c[N];
__device__ __align__(16) float g_e[N];
__device__ float g_t[2];

// ===========================================================================
// helpers
// ===========================================================================
__device__ __forceinline__ uint32_t smem_u32(const void* p) {
    uint32_t a;
    asm("{ .reg .u64 t; cvta.to.shared.u64 t, %1; cvt.u32.u64 %0, t; }"
        : "=r"(a) : "l"(p));
    return a;
}
__device__ __forceinline__ float f2tf32(float x) {
    float y;
    asm("cvt.rna.tf32.f32 %0, %1;" : "=f"(y) : "f"(x));
    return y;
}
#define CP_ASYNC16(smem, gptr) \
    asm volatile("cp.async.cg.shared.global [%0], [%1], 16;" \
                 :: "r"(smem), "l"(gptr) : "memory")
#define CP_COMMIT() asm volatile("cp.async.commit_group;" ::: "memory")
#define CP_WAIT(n)  asm volatile("cp.async.wait_group %0;" :: "n"(n) : "memory")

__device__ __forceinline__ void mma_tf32(float* d, float2 a01, float2 a23,
                                         float2 b01) {
    asm volatile(
        "mma.sync.aligned.m16n8k8.row.col.f32.tf32.tf32.f32 "
        "{%0,%1,%2,%3}, {%4,%5,%6,%7}, {%8,%9}, {%0,%1,%2,%3};"
        : "+f"(d[0]), "+f"(d[1]), "+f"(d[2]), "+f"(d[3])
        : "r"(__float_as_uint(a01.x)), "r"(__float_as_uint(a01.y)),
          "r"(__float_as_uint(a23.x)), "r"(__float_as_uint(a23.y)),
          "r"(__float_as_uint(b01.x)), "r"(__float_as_uint(b01.y)));
}

// ===========================================================================
// Kernel 1: row sums of A -> dinv, c ; sigmoid(theta)
// ===========================================================================
__global__ __launch_bounds__(256) void k_rowsum_A(const float* __restrict__ A,
                                                  const float* __restrict__ theta) {
    int row = blockIdx.x;
    const float4* a4 = (const float4*)(A + (size_t)row * N);
    float s = 0.f;
    for (int i = threadIdx.x; i < N / 4; i += 256) {
        float4 v = a4[i];
        s += v.x + v.y + v.z + v.w;
    }
    __shared__ float red[256];
    red[threadIdx.x] = s;
    __syncthreads();
    for (int o = 128; o > 0; o >>= 1) {
        if (threadIdx.x < o) red[threadIdx.x] += red[threadIdx.x + o];
        __syncthreads();
    }
    if (threadIdx.x == 0) {
        float d = red[0];
        g_dinv[row] = rsqrtf(d);
        g_c[row] = 1.0f / d;
        if (row == 0) {
            g_t[0] = 1.0f / (1.0f + expf(-theta[0]));
            g_t[1] = 1.0f / (1.0f + expf(-theta[1]));
        }
    }
}

// ===========================================================================
// Kernel 2: prep with pair-contiguous layouts (R9-proven).
//   g_AtcP[k][m'] : m-pairs (m, m+8) adjacent, val tf32(A[m][k]*c[k])
//   g_BtP[(k>>3)*4+(k&3)][2n + ((k>>2)&1)] = tf32(A[k][n]), pitch 2N
// ===========================================================================
__global__ __launch_bounds__(256) void k_prep(const float* __restrict__ A) {
    __shared__ float ta[32][33];
    __shared__ float tb[32][33];
    int tx = threadIdx.x, ty = threadIdx.y;
    int x0 = blockIdx.x * 32, y0 = blockIdx.y * 32;
    float cc = g_c[x0 + tx];
#pragma unroll
    for (int r = 0; r < 4; r++) {
        int row = y0 + ty + r * 8;
        float v = A[(size_t)row * N + x0 + tx];
        tb[ty + r * 8][tx] = f2tf32(v);
        ta[ty + r * 8][tx] = f2tf32(v * cc);
    }
    __syncthreads();

    // B writes: k = y0+i, n = x0+j. Pairs (i, i+4) within 8-groups.
#pragma unroll
    for (int rr = 0; rr < 2; rr++) {
        int p = ty + rr * 8;
        int i = 8 * (p >> 2) + (p & 3);
        float2 val = make_float2(tb[i][tx], tb[i + 4][tx]);
        *(float2*)(g_BtP + (size_t)(y0 / 2 + p) * (2 * N) + 2 * (x0 + tx)) = val;
    }
    // A writes: k = x0+j, m = y0+i. Pairs (i, i+8) within 16-blocks.
#pragma unroll
    for (int rr = 0; rr < 2; rr++) {
        int j = 2 * (ty + 8 * rr) + (tx >> 4);
        int q = tx & 15;
        int i = 16 * (q >> 3) + (q & 7);
        int col = y0 + 16 * (q >> 3) + 2 * (q & 7);
        float2 val = make_float2(ta[i][j], ta[i + 8][j]);
        *(float2*)(g_AtcP + (size_t)(x0 + j) * N + col) = val;
    }
}

// ===========================================================================
// dummy no-op: keeps ncu's captured launch index on the GEMM
// ===========================================================================
__global__ void k_nop() {}

// ===========================================================================
// Kernel 3: tf32 mma.sync GEMM — R9 structure (CTA 128x128, 8 warps 4m x 2n,
// warp 32x64, 2-stage cp.async, LDS.64 pair-fragment loads) with the t0*A
// Laplacian term fused into the coalesced epilogue store.
//   M = Atc^T @ Bt ; g_P = dinv_i*dinv_j*(t0*A + t1*M) + I
// ===========================================================================
#define BK 32
#define NCH (N / BK)             // 128
#define PITCHA 136               // == 8 mod 32 (conflict-free)
#define PITCHB 264               // == 8 mod 32 (conflict-free)
#define TILEA_F (BK * PITCHA)        // 32 k-rows x 136
#define TILEB_F ((BK / 2) * PITCHB)  // 16 phys rows x 264
#define STAGE_F (TILEA_F + TILEB_F)  // 8576 floats
#define SMEM_BYTES (2 * STAGE_F * 4) // 68608

__device__ __forceinline__ void stage_chunk(uint32_t sbase, int buf, int ch,
                                            int i0, int j0, int tid) {
    int k0 = ch * BK;
    uint32_t sa = sbase + buf * (STAGE_F * 4);
    uint32_t sb = sa + TILEA_F * 4;
#pragma unroll
    for (int t = 0; t < 4; t++) {
        int id = tid + t * 256;
        int k = id >> 5, seg = id & 31;
        CP_ASYNC16(sa + k * (PITCHA * 4) + seg * 16,
                   g_AtcP + (size_t)(k0 + k) * N + i0 + seg * 4);
    }
#pragma unroll
    for (int t = 0; t < 4; t++) {
        int id = tid + t * 256;
        int r = id >> 6, seg = id & 63;
        CP_ASYNC16(sb + r * (PITCHB * 4) + seg * 16,
                   g_BtP + (size_t)(k0 / 2 + r) * (2 * N) + 2 * j0 + seg * 4);
    }
}

__global__ __launch_bounds__(256, 2) void k_gemm_mma(const float* __restrict__ A) {
    extern __shared__ float sm[];
    uint32_t sbase = smem_u32(sm);
    int tid = threadIdx.x;
    int wid = tid >> 5, lane = tid & 31;
    int g = lane >> 2, tig = lane & 3;
    int wm0 = (wid & 3) * 32, wn0 = (wid >> 2) * 64;
    int i0 = blockIdx.y * 128, j0 = blockIdx.x * 128;

    float acc[2][8][4];
#pragma unroll
    for (int mt = 0; mt < 2; mt++)
#pragma unroll
        for (int j = 0; j < 8; j++)
#pragma unroll
            for (int c = 0; c < 4; c++) acc[mt][j][c] = 0.f;

    stage_chunk(sbase, 0, 0, i0, j0, tid);
    CP_COMMIT();
    stage_chunk(sbase, 1, 1, i0, j0, tid);
    CP_COMMIT();

    for (int ch = 0; ch < NCH; ch++) {
        if (ch < NCH - 1) CP_WAIT(1);
        else              CP_WAIT(0);
        __syncthreads();

        const float* As = sm + (ch & 1) * STAGE_F;
        const float* Bs = As + TILEA_F;
#pragma unroll
        for (int s = 0; s < 4; s++) {
            float2 a01[2], a23[2];
#pragma unroll
            for (int mt = 0; mt < 2; mt++) {
                int col = wm0 + 16 * mt + 2 * g;
                a01[mt] = *(const float2*)(As + (8 * s + tig) * PITCHA + col);
                a23[mt] = *(const float2*)(As + (8 * s + tig + 4) * PITCHA + col);
            }
#pragma unroll
            for (int j = 0; j < 8; j++) {
                float2 b01 = *(const float2*)(Bs + (4 * s + tig) * PITCHB +
                                              2 * (wn0 + 8 * j + g));
                mma_tf32(acc[0][j], a01[0], a23[0], b01);
                mma_tf32(acc[1][j], a01[1], a23[1], b01);
            }
        }
        __syncthreads();
        if (ch + 2 < NCH) {
            stage_chunk(sbase, ch & 1, ch + 2, i0, j0, tid);
            CP_COMMIT();
        }
    }

    // ---- epilogue: t1*M scale + diag via smem transpose; t0*A term added
    //      in the coalesced store phase (float4 loads of A at same coords) ----
    float t1 = g_t[1];
    float t0 = g_t[0];
    float* scr = sm;   // 128 x 132 floats = 67584 B (< 68608)
#pragma unroll
    for (int mt = 0; mt < 2; mt++) {
        int m0 = wm0 + 16 * mt + g;
        int gi0 = i0 + m0, gi1 = gi0 + 8;
        float di0 = t1 * g_dinv[gi0];
        float di1 = t1 * g_dinv[gi1];
#pragma unroll
        for (int j = 0; j < 8; j++) {
            int n = wn0 + 8 * j + 2 * tig;
            int gj = j0 + n;
            float dj0 = g_dinv[gj], dj1 = g_dinv[gj + 1];
            float p00 = acc[mt][j][0] * di0 * dj0;
            float p01 = acc[mt][j][1] * di0 * dj1;
            float p10 = acc[mt][j][2] * di1 * dj0;
            float p11 = acc[mt][j][3] * di1 * dj1;
            if (gi0 == gj) p00 += 1.0f;
            if (gi0 == gj + 1) p01 += 1.0f;
            if (gi1 == gj) p10 += 1.0f;
            if (gi1 == gj + 1) p11 += 1.0f;
            *(float2*)(scr + m0 * 132 + n) = make_float2(p00, p01);
            *(float2*)(scr + (m0 + 8) * 132 + n) = make_float2(p10, p11);
        }
    }
    __syncthreads();
#pragma unroll
    for (int t = 0; t < 16; t++) {
        int id = tid + t * 256;
        int row = id >> 5, cg = id & 31;
        int gi = i0 + row;
        float di = t0 * g_dinv[gi];
        float4 v = *(float4*)(scr + row * 132 + cg * 4);
        float4 av = *(const float4*)(A + (size_t)gi * N + j0 + cg * 4);
        float4 dj = *(const float4*)(g_dinv + j0 + cg * 4);
        v.x += di * dj.x * av.x;
        v.y += di * dj.y * av.y;
        v.z += di * dj.z * av.z;
        v.w += di * dj.w * av.w;
        *(float4*)(g_P + (size_t)gi * N + j0 + cg * 4) = v;
    }
}

// ===========================================================================
// Kernel 4: read-only row-sum of P -> e = rsqrt(rowsum)
// ===========================================================================
__global__ __launch_bounds__(256) void k_rowsum_P() {
    int row = blockIdx.x;
    const float4* p4 = (const float4*)(g_P + (size_t)row * N);
    float s = 0.f;
    for (int i = threadIdx.x; i < N / 4; i += 256) {
        float4 v = p4[i];
        s += v.x + v.y + v.z + v.w;
    }
    __shared__ float red[256];
    red[threadIdx.x] = s;
    __syncthreads();
    for (int o = 128; o > 0; o >>= 1) {
        if (threadIdx.x < o) red[threadIdx.x] += red[threadIdx.x + o];
        __syncthreads();
    }
    if (threadIdx.x == 0) g_e[row] = rsqrtf(red[0]);
}

// ===========================================================================
// Kernel 5: per-row top-k + gather + linear. Fast path (k<=4): all 8 float4
// loads front-batched into registers (MLP=8), then the scalar insertion
// chains in ascending-j order (stable-argsort tie rule preserved).
// ===========================================================================
__global__ __launch_bounds__(256) void k_topk_out(const float* __restrict__ x,
                                                  const float* __restrict__ W,
                                                  const float* __restrict__ b,
                                                  const int* __restrict__ kp,
                                                  float* __restrict__ out) {
    int row = blockIdx.x;
    int tid = threadIdx.x, lane = tid & 31, wid = tid >> 5;
    __shared__ float sv[32];
    __shared__ int si[32];
    __shared__ float selv[16];
    __shared__ int seli[16];
    __shared__ float y[DIN];

    int k = kp ? *kp : 4;
    if (k < 1) k = 1;
    if (k > 16) k = 16;

    const float* prow = g_P + (size_t)row * N;

    if (k <= 4) {
        // batch ALL loads first (independent -> high MLP)
        float4 pv[4], ev[4];
#pragma unroll
        for (int it = 0; it < 4; it++) {
            int j = (it * 256 + tid) * 4;
            pv[it] = *(const float4*)(prow + j);
            ev[it] = *(const float4*)(g_e + j);
        }
        float v0 = NEG_HUGE, v1 = NEG_HUGE, v2 = NEG_HUGE, v3 = NEG_HUGE;
        int i0 = N, i1 = N, i2 = N, i3 = N;
#pragma unroll
        for (int it = 0; it < 4; it++) {
            int j = (it * 256 + tid) * 4;
            float vv[4] = {pv[it].x * ev[it].x, pv[it].y * ev[it].y,
                           pv[it].z * ev[it].z, pv[it].w * ev[it].w};
#pragma unroll
            for (int u = 0; u < 4; u++) {
                float v = vv[u];
                int idx = j + u;
                if (v > v3) {
                    if (v > v0) {
                        v3 = v2; i3 = i2; v2 = v1; i2 = i1;
                        v1 = v0; i1 = i0; v0 = v; i0 = idx;
                    } else if (v > v1) {
                        v3 = v2; i3 = i2; v2 = v1; i2 = i1;
                        v1 = v; i1 = idx;
                    } else if (v > v2) {
                        v3 = v2; i3 = i2; v2 = v; i2 = idx;
                    } else {
                        v3 = v; i3 = idx;
                    }
                }
            }
        }
#pragma unroll
        for (int r = 0; r < 4; r++) {
            float bv = v0;
            int bi = i0;
#pragma unroll
            for (int o = 16; o > 0; o >>= 1) {
                float ov = __shfl_xor_sync(0xFFFFFFFF, bv, o);
                int oi = __shfl_xor_sync(0xFFFFFFFF, bi, o);
                if (ov > bv || (ov == bv && oi < bi)) { bv = ov; bi = oi; }
            }
            if (v0 == bv && i0 == bi) {
                v0 = v1; i0 = i1; v1 = v2; i1 = i2;
                v2 = v3; i2 = i3; v3 = NEG_HUGE; i3 = N;
            }
            if (lane == 0) { sv[wid * 4 + r] = bv; si[wid * 4 + r] = bi; }
        }
        __syncthreads();
        if (wid == 0) {
            int h = 0;
            float cv = (lane < 8) ? sv[lane * 4] : NEG_HUGE;
            int ci = (lane < 8) ? si[lane * 4] : N;
#pragma unroll
            for (int r = 0; r < 4; r++) {
                float bv = cv;
                int bi = ci;
#pragma unroll
                for (int o = 16; o > 0; o >>= 1) {
                    float ov = __shfl_xor_sync(0xFFFFFFFF, bv, o);
                    int oi = __shfl_xor_sync(0xFFFFFFFF, bi, o);
                    if (ov > bv || (ov == bv && oi < bi)) { bv = ov; bi = oi; }
                }
                if (lane < 8 && cv == bv && ci == bi) {
                    h++;
                    cv = (h < 4) ? sv[lane * 4 + h] : NEG_HUGE;
                    ci = (h < 4) ? si[lane * 4 + h] : N;
                }
                if (lane == 0) { selv[r] = bv; seli[r] = bi; }
            }
        }
        __syncthreads();
    } else {
        // generic multi-pass path; scratch in g_AtcP (dead after GEMM)
        __shared__ float rv[256];
        __shared__ int ri[256];
        float* vbuf = g_AtcP + (size_t)row * N;
        for (int j = tid; j < N; j += 256) vbuf[j] = g_e[j] * prow[j];
        __syncthreads();
        for (int s = 0; s < k; s++) {
            float bv = NEG_HUGE;
            int bi = N;
            for (int j = tid; j < N; j += 256) {
                float val = vbuf[j];
                if (val > bv) { bv = val; bi = j; }
            }
            rv[tid] = bv; ri[tid] = bi;
            __syncthreads();
            for (int o = 128; o > 0; o >>= 1) {
                if (tid < o) {
                    float ov = rv[tid + o]; int oi = ri[tid + o];
                    if (ov > rv[tid] || (ov == rv[tid] && oi < ri[tid])) {
                        rv[tid] = ov; ri[tid] = oi;
                    }
                }
                __syncthreads();
            }
            if (tid == 0) {
                seli[s] = ri[0]; selv[s] = rv[0];
                vbuf[ri[0]] = NEG_HUGE;
            }
            __syncthreads();
        }
    }

    float ei = g_e[row];
    if (tid < DIN) {
        float acc = 0.f;
        for (int s = 0; s < k; s++)
            acc += (ei * selv[s]) * x[(size_t)seli[s] * DIN + tid];
        y[tid] = acc;
    }
    __syncthreads();
    if (tid < DOUT) {
        float acc = b[tid];
        const float* wr = W + tid * DIN;
#pragma unroll
        for (int f = 0; f < DIN; f++) acc += y[f] * wr[f];
        out[(size_t)row * DOUT + tid] = acc;
    }
}

// ===========================================================================
extern "C" void kernel_launch(void* const* d_in, const int* in_sizes, int n_in,
                              void* d_out, int out_size) {
    const float* x = (const float*)d_in[0];
    const float* A = (const float*)d_in[1];
    const float* theta = (const float*)d_in[2];
    const float* W = (const float*)d_in[3];
    const float* b = (const float*)d_in[4];
    const int* kp = (n_in > 5) ? (const int*)d_in[5] : nullptr;
    float* out = (float*)d_out;

    static bool attr_set = false;
    if (!attr_set) {
        cudaFuncSetAttribute(k_gemm_mma, cudaFuncAttributeMaxDynamicSharedMemorySize,
                             SMEM_BYTES);
        attr_set = true;
    }

    k_rowsum_A<<<N, 256>>>(A, theta);
    dim3 pb(32, 8);
    dim3 pg(N / 32, N / 32);
    k_prep<<<pg, pb>>>(A);
    k_nop<<<1, 32>>>();                    // keeps ncu capture on the GEMM
    dim3 gg(N / 128, N / 128);
    k_gemm_mma<<<gg, 256, SMEM_BYTES>>>(A);
    k_rowsum_P<<<N, 256>>>();
    k_topk_out<<<N, 256>>>(x, W, b, kp, out);
}

// round 14
// speedup vs baseline: 1.2441x; 1.0829x over previous
#include <cuda_runtime.h>
#include <cstdint>
#include <math.h>

#define N 4096
#define DIN 64
#define DOUT 64
#define NEG_HUGE (-3.402823466e38f)

// ---- scratch (device globals; no runtime allocation) ----
__device__ __align__(16) float g_P[(size_t)N * N];     // 64 MB: final P
// A operand, [k][m'] with m-pairs (m, m+8) adjacent within 16-blocks
__device__ __align__(16) float g_AtcP[(size_t)N * N];  // also topk scratch later
// B operand, k-folded: phys row = (k>>3)*4 + (k&3), col = 2n + ((k>>2)&1)
__device__ __align__(16) float g_BtP[(size_t)N * N];   // (N/2) rows x 2N cols
__device__ __align__(16) float g_dinv[N];
__device__ __align__(16) float g_c[N];
__device__ __align__(16) float g_e[N];
__device__ float g_t[2];

// ===========================================================================
// helpers
// ===========================================================================
__device__ __forceinline__ uint32_t smem_u32(const void* p) {
    uint32_t a;
    asm("{ .reg .u64 t; cvta.to.shared.u64 t, %1; cvt.u32.u64 %0, t; }"
        : "=r"(a) : "l"(p));
    return a;
}
__device__ __forceinline__ float f2tf32(float x) {
    float y;
    asm("cvt.rna.tf32.f32 %0, %1;" : "=f"(y) : "f"(x));
    return y;
}
#define CP_ASYNC16(smem, gptr) \
    asm volatile("cp.async.cg.shared.global [%0], [%1], 16;" \
                 :: "r"(smem), "l"(gptr) : "memory")
#define CP_COMMIT() asm volatile("cp.async.commit_group;" ::: "memory")
#define CP_WAIT(n)  asm volatile("cp.async.wait_group %0;" :: "n"(n) : "memory")

__device__ __forceinline__ void mma_tf32(float* d, float2 a01, float2 a23,
                                         float2 b01) {
    asm volatile(
        "mma.sync.aligned.m16n8k8.row.col.f32.tf32.tf32.f32 "
        "{%0,%1,%2,%3}, {%4,%5,%6,%7}, {%8,%9}, {%0,%1,%2,%3};"
        : "+f"(d[0]), "+f"(d[1]), "+f"(d[2]), "+f"(d[3])
        : "r"(__float_as_uint(a01.x)), "r"(__float_as_uint(a01.y)),
          "r"(__float_as_uint(a23.x)), "r"(__float_as_uint(a23.y)),
          "r"(__float_as_uint(b01.x)), "r"(__float_as_uint(b01.y)));
}

// ===========================================================================
// Kernel 1: row sums of A -> dinv, c ; sigmoid(theta)
// ===========================================================================
__global__ __launch_bounds__(256) void k_rowsum_A(const float* __restrict__ A,
                                                  const float* __restrict__ theta) {
    int row = blockIdx.x;
    const float4* a4 = (const float4*)(A + (size_t)row * N);
    float s = 0.f;
    for (int i = threadIdx.x; i < N / 4; i += 256) {
        float4 v = a4[i];
        s += v.x + v.y + v.z + v.w;
    }
    __shared__ float red[256];
    red[threadIdx.x] = s;
    __syncthreads();
    for (int o = 128; o > 0; o >>= 1) {
        if (threadIdx.x < o) red[threadIdx.x] += red[threadIdx.x + o];
        __syncthreads();
    }
    if (threadIdx.x == 0) {
        float d = red[0];
        g_dinv[row] = rsqrtf(d);
        g_c[row] = 1.0f / d;
        if (row == 0) {
            g_t[0] = 1.0f / (1.0f + expf(-theta[0]));
            g_t[1] = 1.0f / (1.0f + expf(-theta[1]));
        }
    }
}

// ===========================================================================
// Kernel 2: prep with pair-contiguous layouts (R9-proven).
// ===========================================================================
__global__ __launch_bounds__(256) void k_prep(const float* __restrict__ A) {
    __shared__ float ta[32][33];
    __shared__ float tb[32][33];
    int tx = threadIdx.x, ty = threadIdx.y;
    int x0 = blockIdx.x * 32, y0 = blockIdx.y * 32;
    float cc = g_c[x0 + tx];
#pragma unroll
    for (int r = 0; r < 4; r++) {
        int row = y0 + ty + r * 8;
        float v = A[(size_t)row * N + x0 + tx];
        tb[ty + r * 8][tx] = f2tf32(v);
        ta[ty + r * 8][tx] = f2tf32(v * cc);
    }
    __syncthreads();
#pragma unroll
    for (int rr = 0; rr < 2; rr++) {
        int p = ty + rr * 8;
        int i = 8 * (p >> 2) + (p & 3);
        float2 val = make_float2(tb[i][tx], tb[i + 4][tx]);
        *(float2*)(g_BtP + (size_t)(y0 / 2 + p) * (2 * N) + 2 * (x0 + tx)) = val;
    }
#pragma unroll
    for (int rr = 0; rr < 2; rr++) {
        int j = 2 * (ty + 8 * rr) + (tx >> 4);
        int q = tx & 15;
        int i = 16 * (q >> 3) + (q & 7);
        int col = y0 + 16 * (q >> 3) + 2 * (q & 7);
        float2 val = make_float2(ta[i][j], ta[i + 8][j]);
        *(float2*)(g_AtcP + (size_t)(x0 + j) * N + col) = val;
    }
}

// ===========================================================================
// dummy no-op: keeps ncu's captured launch index on the GEMM
// ===========================================================================
__global__ void k_nop() {}

// ===========================================================================
// Kernel 3: tf32 mma.sync GEMM — R11 version (CTA 128x128, LDS.64 pair
// fragments, fused t0*A epilogue).  g_P = dinv_i*dinv_j*(t0*A + t1*M) + I
// ===========================================================================
#define BK 32
#define NCH (N / BK)
#define PITCHA 136
#define PITCHB 264
#define TILEA_F (BK * PITCHA)
#define TILEB_F ((BK / 2) * PITCHB)
#define STAGE_F (TILEA_F + TILEB_F)
#define SMEM_BYTES (2 * STAGE_F * 4)

__device__ __forceinline__ void stage_chunk(uint32_t sbase, int buf, int ch,
                                            int i0, int j0, int tid) {
    int k0 = ch * BK;
    uint32_t sa = sbase + buf * (STAGE_F * 4);
    uint32_t sb = sa + TILEA_F * 4;
#pragma unroll
    for (int t = 0; t < 4; t++) {
        int id = tid + t * 256;
        int k = id >> 5, seg = id & 31;
        CP_ASYNC16(sa + k * (PITCHA * 4) + seg * 16,
                   g_AtcP + (size_t)(k0 + k) * N + i0 + seg * 4);
    }
#pragma unroll
    for (int t = 0; t < 4; t++) {
        int id = tid + t * 256;
        int r = id >> 6, seg = id & 63;
        CP_ASYNC16(sb + r * (PITCHB * 4) + seg * 16,
                   g_BtP + (size_t)(k0 / 2 + r) * (2 * N) + 2 * j0 + seg * 4);
    }
}

__global__ __launch_bounds__(256, 2) void k_gemm_mma(const float* __restrict__ A) {
    extern __shared__ float sm[];
    uint32_t sbase = smem_u32(sm);
    int tid = threadIdx.x;
    int wid = tid >> 5, lane = tid & 31;
    int g = lane >> 2, tig = lane & 3;
    int wm0 = (wid & 3) * 32, wn0 = (wid >> 2) * 64;
    int i0 = blockIdx.y * 128, j0 = blockIdx.x * 128;

    float acc[2][8][4];
#pragma unroll
    for (int mt = 0; mt < 2; mt++)
#pragma unroll
        for (int j = 0; j < 8; j++)
#pragma unroll
            for (int c = 0; c < 4; c++) acc[mt][j][c] = 0.f;

    stage_chunk(sbase, 0, 0, i0, j0, tid);
    CP_COMMIT();
    stage_chunk(sbase, 1, 1, i0, j0, tid);
    CP_COMMIT();

    for (int ch = 0; ch < NCH; ch++) {
        if (ch < NCH - 1) CP_WAIT(1);
        else              CP_WAIT(0);
        __syncthreads();

        const float* As = sm + (ch & 1) * STAGE_F;
        const float* Bs = As + TILEA_F;
#pragma unroll
        for (int s = 0; s < 4; s++) {
            float2 a01[2], a23[2];
#pragma unroll
            for (int mt = 0; mt < 2; mt++) {
                int col = wm0 + 16 * mt + 2 * g;
                a01[mt] = *(const float2*)(As + (8 * s + tig) * PITCHA + col);
                a23[mt] = *(const float2*)(As + (8 * s + tig + 4) * PITCHA + col);
            }
#pragma unroll
            for (int j = 0; j < 8; j++) {
                float2 b01 = *(const float2*)(Bs + (4 * s + tig) * PITCHB +
                                              2 * (wn0 + 8 * j + g));
                mma_tf32(acc[0][j], a01[0], a23[0], b01);
                mma_tf32(acc[1][j], a01[1], a23[1], b01);
            }
        }
        __syncthreads();
        if (ch + 2 < NCH) {
            stage_chunk(sbase, ch & 1, ch + 2, i0, j0, tid);
            CP_COMMIT();
        }
    }

    float t1 = g_t[1];
    float t0 = g_t[0];
    float* scr = sm;
#pragma unroll
    for (int mt = 0; mt < 2; mt++) {
        int m0 = wm0 + 16 * mt + g;
        int gi0 = i0 + m0, gi1 = gi0 + 8;
        float di0 = t1 * g_dinv[gi0];
        float di1 = t1 * g_dinv[gi1];
#pragma unroll
        for (int j = 0; j < 8; j++) {
            int n = wn0 + 8 * j + 2 * tig;
            int gj = j0 + n;
            float dj0 = g_dinv[gj], dj1 = g_dinv[gj + 1];
            float p00 = acc[mt][j][0] * di0 * dj0;
            float p01 = acc[mt][j][1] * di0 * dj1;
            float p10 = acc[mt][j][2] * di1 * dj0;
            float p11 = acc[mt][j][3] * di1 * dj1;
            if (gi0 == gj) p00 += 1.0f;
            if (gi0 == gj + 1) p01 += 1.0f;
            if (gi1 == gj) p10 += 1.0f;
            if (gi1 == gj + 1) p11 += 1.0f;
            *(float2*)(scr + m0 * 132 + n) = make_float2(p00, p01);
            *(float2*)(scr + (m0 + 8) * 132 + n) = make_float2(p10, p11);
        }
    }
    __syncthreads();
#pragma unroll
    for (int t = 0; t < 16; t++) {
        int id = tid + t * 256;
        int row = id >> 5, cg = id & 31;
        int gi = i0 + row;
        float di = t0 * g_dinv[gi];
        float4 v = *(float4*)(scr + row * 132 + cg * 4);
        float4 av = *(const float4*)(A + (size_t)gi * N + j0 + cg * 4);
        float4 dj = *(const float4*)(g_dinv + j0 + cg * 4);
        v.x += di * dj.x * av.x;
        v.y += di * dj.y * av.y;
        v.z += di * dj.z * av.z;
        v.w += di * dj.w * av.w;
        *(float4*)(g_P + (size_t)gi * N + j0 + cg * 4) = v;
    }
}

// ===========================================================================
// Kernel 4: read-only row-sum of P -> e = rsqrt(rowsum)
// ===========================================================================
__global__ __launch_bounds__(256) void k_rowsum_P() {
    int row = blockIdx.x;
    const float4* p4 = (const float4*)(g_P + (size_t)row * N);
    float s = 0.f;
    for (int i = threadIdx.x; i < N / 4; i += 256) {
        float4 v = p4[i];
        s += v.x + v.y + v.z + v.w;
    }
    __shared__ float red[256];
    red[threadIdx.x] = s;
    __syncthreads();
    for (int o = 128; o > 0; o >>= 1) {
        if (threadIdx.x < o) red[threadIdx.x] += red[threadIdx.x + o];
        __syncthreads();
    }
    if (threadIdx.x == 0) g_e[row] = rsqrtf(red[0]);
}

// ===========================================================================
// Kernel 5: WARP-PER-ROW top-k + gather + linear.
// 512 blocks x 8 warps; one warp owns one row; no block barriers after the
// one-time W preload. Fast path (k<=4) entirely in registers + shuffles.
// ===========================================================================
__global__ __launch_bounds__(256) void k_topk_out(const float* __restrict__ x,
                                                  const float* __restrict__ W,
                                                  const float* __restrict__ b,
                                                  const int* __restrict__ kp,
                                                  float* __restrict__ out) {
    __shared__ float Ws[64 * 65];      // Ws[f*65 + o] = W[o][f]
    __shared__ float selw[8][16];
    __shared__ int seliw[8][16];

    int tid = threadIdx.x, lane = tid & 31, wid = tid >> 5;
    int row = blockIdx.x * 8 + wid;

    // one-time cooperative W preload (transposed, pitch 65)
    for (int idx = tid; idx < 64 * 64; idx += 256) {
        int o = idx >> 6, f = idx & 63;
        Ws[f * 65 + o] = W[idx];
    }
    __syncthreads();

    int k = kp ? *kp : 4;
    if (k < 1) k = 1;
    if (k > 16) k = 16;

    const float* prow = g_P + (size_t)row * N;

    if (k <= 4) {
        float v0 = NEG_HUGE, v1 = NEG_HUGE, v2 = NEG_HUGE, v3 = NEG_HUGE;
        int i0 = N, i1 = N, i2 = N, i3 = N;
#pragma unroll
        for (int gq = 0; gq < 8; gq++) {
            float4 pv[4], ev[4];
#pragma unroll
            for (int q = 0; q < 4; q++) {
                int j = ((gq * 4 + q) * 32 + lane) * 4;
                pv[q] = *(const float4*)(prow + j);
                ev[q] = *(const float4*)(g_e + j);
            }
#pragma unroll
            for (int q = 0; q < 4; q++) {
                int j = ((gq * 4 + q) * 32 + lane) * 4;
                float vv[4] = {pv[q].x * ev[q].x, pv[q].y * ev[q].y,
                               pv[q].z * ev[q].z, pv[q].w * ev[q].w};
#pragma unroll
                for (int u = 0; u < 4; u++) {
                    float v = vv[u];
                    int idx = j + u;
                    // per-lane stream indices strictly ascend -> strict >
                    if (v > v3) {
                        if (v > v0) {
                            v3 = v2; i3 = i2; v2 = v1; i2 = i1;
                            v1 = v0; i1 = i0; v0 = v; i0 = idx;
                        } else if (v > v1) {
                            v3 = v2; i3 = i2; v2 = v1; i2 = i1;
                            v1 = v; i1 = idx;
                        } else if (v > v2) {
                            v3 = v2; i3 = i2; v2 = v; i2 = idx;
                        } else {
                            v3 = v; i3 = idx;
                        }
                    }
                }
            }
        }
        // warp merge: 4 rounds of shuffle-argmax, pop by static shift
#pragma unroll
        for (int r = 0; r < 4; r++) {
            float bv = v0;
            int bi = i0;
#pragma unroll
            for (int o = 16; o > 0; o >>= 1) {
                float ov = __shfl_xor_sync(0xFFFFFFFF, bv, o);
                int oi = __shfl_xor_sync(0xFFFFFFFF, bi, o);
                if (ov > bv || (ov == bv && oi < bi)) { bv = ov; bi = oi; }
            }
            if (v0 == bv && i0 == bi) {   // winner (unique index) pops head
                v0 = v1; i0 = i1; v1 = v2; i1 = i2;
                v2 = v3; i2 = i3; v3 = NEG_HUGE; i3 = N;
            }
            if (lane == 0) { selw[wid][r] = bv; seliw[wid][r] = bi; }
        }
        __syncwarp();
    } else {
        // generic per-warp multi-pass (fallback; scratch in g_AtcP)
        float* vbuf = g_AtcP + (size_t)row * N;
        for (int j = lane; j < N; j += 32) vbuf[j] = g_e[j] * prow[j];
        __syncwarp();
        for (int s = 0; s < k; s++) {
            float bv = NEG_HUGE;
            int bi = N;
            for (int j = lane; j < N; j += 32) {
                float v = *(volatile float*)(vbuf + j);
                if (v > bv) { bv = v; bi = j; }
            }
#pragma unroll
            for (int o = 16; o > 0; o >>= 1) {
                float ov = __shfl_xor_sync(0xFFFFFFFF, bv, o);
                int oi = __shfl_xor_sync(0xFFFFFFFF, bi, o);
                if (ov > bv || (ov == bv && oi < bi)) { bv = ov; bi = oi; }
            }
            if (lane == 0) {
                selw[wid][s] = bv;
                seliw[wid][s] = bi;
                *(volatile float*)(vbuf + bi) = NEG_HUGE;
            }
            __syncwarp();
        }
    }

    // ---- gather + linear, all by this warp (order matches old code) ----
    float ei = g_e[row];
    float y0 = 0.f, y1 = 0.f;
    for (int s = 0; s < k; s++) {
        float w = ei * selw[wid][s];
        int idx = seliw[wid][s];
        y0 += w * x[(size_t)idx * DIN + lane];
        y1 += w * x[(size_t)idx * DIN + lane + 32];
    }
    float acc0 = b[lane], acc1 = b[lane + 32];
#pragma unroll
    for (int f = 0; f < 32; f++) {
        float yf = __shfl_sync(0xFFFFFFFF, y0, f);
        acc0 += yf * Ws[f * 65 + lane];
        acc1 += yf * Ws[f * 65 + lane + 32];
    }
#pragma unroll
    for (int f = 0; f < 32; f++) {
        float yf = __shfl_sync(0xFFFFFFFF, y1, f);
        acc0 += yf * Ws[(f + 32) * 65 + lane];
        acc1 += yf * Ws[(f + 32) * 65 + lane + 32];
    }
    out[(size_t)row * DOUT + lane] = acc0;
    out[(size_t)row * DOUT + lane + 32] = acc1;
}

// ===========================================================================
extern "C" void kernel_launch(void* const* d_in, const int* in_sizes, int n_in,
                              void* d_out, int out_size) {
    const float* x = (const float*)d_in[0];
    const float* A = (const float*)d_in[1];
    const float* theta = (const float*)d_in[2];
    const float* W = (const float*)d_in[3];
    const float* b = (const float*)d_in[4];
    const int* kp = (n_in > 5) ? (const int*)d_in[5] : nullptr;
    float* out = (float*)d_out;

    static bool attr_set = false;
    if (!attr_set) {
        cudaFuncSetAttribute(k_gemm_mma, cudaFuncAttributeMaxDynamicSharedMemorySize,
                             SMEM_BYTES);
        attr_set = true;
    }

    k_rowsum_A<<<N, 256>>>(A, theta);
    dim3 pb(32, 8);
    dim3 pg(N / 32, N / 32);
    k_prep<<<pg, pb>>>(A);
    k_nop<<<1, 32>>>();                    // keeps ncu capture on the GEMM
    dim3 gg(N / 128, N / 128);
    k_gemm_mma<<<gg, 256, SMEM_BYTES>>>(A);
    k_rowsum_P<<<N, 256>>>();
    k_topk_out<<<N / 8, 256>>>(x, W, b, kp, out);
}